// round 13
// baseline (speedup 1.0000x reference)
#include <cuda_runtime.h>

// ZNCC fused, warp-per-channel sliding-window (R12 mainloop, verbatim body)
// with 64-row strips processed as two 32-row halves sharing one smem plane.
// -> 1280 CTAs = single wave at 9 CTAs/SM; warmup amortized over 2x rows.
// CTA = 96 threads = 3 warps; warp w handles channel w of one
// (batch, strip, col-group) tile: 64 raw cols (2/lane) x 64 output rows.
//
// math per pixel (zero-padded 5x5 means):
//   mx = box(x), my = box(y); xc = x-mx, yc = y-my (forced 0 outside image)
//   ncc = Sxy / (sqrt(Sxx*Syy) + 25e-8),  S* = 5x5 sums of products
//   out = mean_c(ncc)

#define HH 512
#define WW 512
#define CHAN 3
#define SSTRIP 64
#define SSHALF 32
#define NSTRIPS (HH / SSTRIP)          // 8
#define OUTCOLS 56
#define NGROUPS 10                     // 10*56 = 560 >= 512
#define NBATCH 16
#define NCTAS (NGROUPS * NSTRIPS * NBATCH)   // 1280
#define PSTRIDE 58                     // plane row stride (even -> float2 ops)

// CINT: all 64 raw columns inside image (groups 1..8)
// RINT: all raw rows r0-4 .. r0+71 inside image (strips 1..6)
template<bool CINT, bool RINT>
__device__ __forceinline__ void zncc_tile(
    const float* __restrict__ xb, const float* __restrict__ yb,
    float (*planes)[SSHALF][PSTRIDE],          // [CHAN][32][PSTRIDE]
    float* __restrict__ outp,                  // batch output base
    int r0, int g, int tid, int ch, int lane,
    float mA, float mB, bool outLane, int gca_c, int pcol)
{
    const unsigned FULL = 0xFFFFFFFFu;
    const float inv25 = 1.0f / 25.0f;
    const float inv3  = 1.0f / 3.0f;
    float (*plane)[PSTRIDE] = planes[ch];

    // ring buffers (indices static after unroll-by-5)
    float hxA[5], hxB[5], hyA[5], hyB[5];
    float qxyA[5], qxyB[5], qxxA[5], qxxB[5], qyyA[5], qyyB[5];
    #pragma unroll
    for (int i = 0; i < 5; i++) {
        hxA[i] = hxB[i] = hyA[i] = hyB[i] = 0.f;
        qxyA[i] = qxyB[i] = qxxA[i] = qxxB[i] = qyyA[i] = qyyB[i] = 0.f;
    }
    float sHxA = 0.f, sHxB = 0.f, sHyA = 0.f, sHyB = 0.f;

    // staged next-row values (software prefetch)
    float2 nvx = make_float2(0.f, 0.f), nvy = make_float2(0.f, 0.f);
    {
        const int t0 = r0 - 4;
        if (RINT || t0 >= 0) {
            nvx = *(const float2*)(xb + (size_t)t0 * WW + gca_c);
            nvy = *(const float2*)(yb + (size_t)t0 * WW + gca_c);
        }
    }

    // one 5-step block; rowOff maps s -> plane row (8 in half 0, 40 in half 1)
    auto run_blocks = [&](int sbStart, int sbEnd, int rowOff) {
        for (int sb = sbStart; sb < sbEnd; sb += 5) {
            #pragma unroll
            for (int k = 0; k < 5; k++) {
                const int s = sb + k;                 // s % 5 == k
                const int t = r0 - 4 + s;             // raw row consumed now
                const int tn = t + 1;                 // prefetch target row

                // base address of row tn (used by prefetch and center reload)
                const float* xrow = xb + (size_t)tn * WW + gca_c;
                const float* yrow = yb + (size_t)tn * WW + gca_c;

                // ---- center row (t-2) reload: L1-resident ----
                float2 cvx, cvy;
                if (RINT) {
                    cvx = *(const float2*)(xrow - 3 * WW);
                    cvy = *(const float2*)(yrow - 3 * WW);
                } else {
                    const int tcl = min(max(t - 2, 0), HH - 1);
                    cvx = *(const float2*)(xb + (size_t)tcl * WW + gca_c);
                    cvy = *(const float2*)(yb + (size_t)tcl * WW + gca_c);
                }

                // ---- consume staged row t, issue loads for row t+1 ----
                float vxA, vxB, vyA, vyB;
                if (CINT) {
                    vxA = nvx.x; vxB = nvx.y;
                    vyA = nvy.x; vyB = nvy.y;
                } else {
                    vxA = nvx.x * mA; vxB = nvx.y * mB;
                    vyA = nvy.x * mA; vyB = nvy.y * mB;
                }
                if (RINT || (unsigned)tn < (unsigned)HH) {
                    nvx = *(const float2*)xrow;
                    nvy = *(const float2*)yrow;
                } else {
                    nvx = make_float2(0.f, 0.f);
                    nvy = make_float2(0.f, 0.f);
                }
                if (!RINT) {
                    if (t < 0) { vxA = vxB = vyA = vyB = 0.f; }
                }

                // ---- horizontal 5-sums of x,y via shuffles ----
                float vxAm = __shfl_up_sync(FULL, vxA, 1);
                float vxBm = __shfl_up_sync(FULL, vxB, 1);
                float vxAp = __shfl_down_sync(FULL, vxA, 1);
                float vxBp = __shfl_down_sync(FULL, vxB, 1);
                float cx   = vxBm + vxA + vxB + vxAp;
                float hxEn = cx + vxAm;               // col A (2l)
                float hxOn = cx + vxBp;               // col B (2l+1)

                float vyAm = __shfl_up_sync(FULL, vyA, 1);
                float vyBm = __shfl_up_sync(FULL, vyB, 1);
                float vyAp = __shfl_down_sync(FULL, vyA, 1);
                float vyBp = __shfl_down_sync(FULL, vyB, 1);
                float cy   = vyBm + vyA + vyB + vyAp;
                float hyEn = cy + vyAm;
                float hyOn = cy + vyBp;

                // ---- vertical sliding sums of h ----
                sHxA += hxEn - hxA[k]; hxA[k] = hxEn;
                sHxB += hxOn - hxB[k]; hxB[k] = hxOn;
                sHyA += hyEn - hyA[k]; hyA[k] = hyEn;
                sHyB += hyOn - hyB[k]; hyB[k] = hyOn;

                if (s >= 4) {
                    // centered values at row tm = t-2 (center from L1 reload)
                    float xcA, xcB, ycA, ycB;
                    if (CINT && RINT) {
                        xcA = fmaf(sHxA, -inv25, cvx.x);
                        xcB = fmaf(sHxB, -inv25, cvx.y);
                        ycA = fmaf(sHyA, -inv25, cvy.x);
                        ycB = fmaf(sHyB, -inv25, cvy.y);
                    } else {
                        const int tm = t - 2;
                        const float rm = (RINT || ((unsigned)tm < (unsigned)HH)) ? 1.0f : 0.0f;
                        const float fmA = CINT ? rm : mA * rm;
                        const float fmB = CINT ? rm : mB * rm;
                        xcA = fmaf(sHxA, -inv25, cvx.x) * fmA;
                        xcB = fmaf(sHxB, -inv25, cvx.y) * fmB;
                        ycA = fmaf(sHyA, -inv25, cvy.x) * fmA;
                        ycB = fmaf(sHyB, -inv25, cvy.y) * fmB;
                    }

                    // neighbors of xc,yc
                    float xcAm = __shfl_up_sync(FULL, xcA, 1);
                    float xcBm = __shfl_up_sync(FULL, xcB, 1);
                    float xcAp = __shfl_down_sync(FULL, xcA, 1);
                    float xcBp = __shfl_down_sync(FULL, xcB, 1);
                    float ycAm = __shfl_up_sync(FULL, ycA, 1);
                    float ycBm = __shfl_up_sync(FULL, ycB, 1);
                    float ycAp = __shfl_down_sync(FULL, ycA, 1);
                    float ycBp = __shfl_down_sync(FULL, ycB, 1);

                    // horizontal 5-sums of products (shared middle-4 term)
                    float c4xy = xcBm * ycBm + xcA * ycA + xcB * ycB + xcAp * ycAp;
                    qxyA[k] = c4xy + xcAm * ycAm;
                    qxyB[k] = c4xy + xcBp * ycBp;
                    float c4xx = xcBm * xcBm + xcA * xcA + xcB * xcB + xcAp * xcAp;
                    qxxA[k] = c4xx + xcAm * xcAm;
                    qxxB[k] = c4xx + xcBp * xcBp;
                    float c4yy = ycBm * ycBm + ycA * ycA + ycB * ycB + ycAp * ycAp;
                    qyyA[k] = c4yy + ycAm * ycAm;
                    qyyB[k] = c4yy + ycBp * ycBp;

                    const int prow = s - rowOff;      // plane row this half
                    if (prow >= 0 && prow < SSHALF) {
                        // direct 5-term vertical sums from the rings
                        float Sxy_A = ((qxyA[0] + qxyA[1]) + (qxyA[2] + qxyA[3])) + qxyA[4];
                        float Sxy_B = ((qxyB[0] + qxyB[1]) + (qxyB[2] + qxyB[3])) + qxyB[4];
                        float Sxx_A = ((qxxA[0] + qxxA[1]) + (qxxA[2] + qxxA[3])) + qxxA[4];
                        float Sxx_B = ((qxxB[0] + qxxB[1]) + (qxxB[2] + qxxB[3])) + qxxB[4];
                        float Syy_A = ((qyyA[0] + qyyA[1]) + (qyyA[2] + qyyA[3])) + qyyA[4];
                        float Syy_B = ((qyyB[0] + qyyB[1]) + (qyyB[2] + qyyB[3])) + qyyB[4];

                        float dA = sqrtf(fmaxf(Sxx_A * Syy_A, 0.f)) + 2.5e-7f;
                        float dB = sqrtf(fmaxf(Sxx_B * Syy_B, 0.f)) + 2.5e-7f;
                        float nA = __fdividef(Sxy_A, dA);
                        float nB = __fdividef(Sxy_B, dB);
                        if (outLane) {
                            *(float2*)&plane[prow][pcol] = make_float2(nA, nB);
                        }
                    }
                }
            }
        }
    };

    // combine the 3 channel planes for one 32-row half (fixed order -> det.)
    auto combine = [&](int half) {
        __syncthreads();   // all plane writes of this half done
        float* op = outp + (size_t)(r0 + SSHALF * half) * WW + g * OUTCOLS;
        for (int idx = tid; idx < SSHALF * (OUTCOLS / 2); idx += 96) {
            int row = idx / (OUTCOLS / 2);
            int c2  = idx - row * (OUTCOLS / 2);
            int col = 2 * c2;
            if (g * OUTCOLS + col < WW) {
                float2 p0 = *(const float2*)&planes[0][row][col];
                float2 p1 = *(const float2*)&planes[1][row][col];
                float2 p2 = *(const float2*)&planes[2][row][col];
                float2 v;
                v.x = (p0.x + p1.x + p2.x) * inv3;
                v.y = (p0.y + p1.y + p2.y) * inv3;
                *(float2*)&op[(size_t)row * WW + col] = v;
            }
        }
        __syncthreads();   // plane free for next half
    };

    run_blocks(0, 40, 8);      // outputs rows 0..31  (s = 8..39)
    combine(0);
    run_blocks(40, 75, 40);    // outputs rows 32..63 (s = 40..71; 72..74 idle)
    combine(1);
}

__global__ __launch_bounds__(96, 9)
void zncc_warp_kernel(const float* __restrict__ xg,
                      const float* __restrict__ yg,
                      float* __restrict__ outg)
{
    __shared__ float plane[CHAN][SSHALF][PSTRIDE];

    const int tid  = threadIdx.x;
    const int lane = tid & 31;
    const int ch   = tid >> 5;          // warp id == channel

    const int task  = blockIdx.x;
    const int b     = task / (NGROUPS * NSTRIPS);
    const int rem   = task - b * (NGROUPS * NSTRIPS);
    const int strip = rem / NGROUPS;
    const int g     = rem - strip * NGROUPS;

    const int r0  = strip * SSTRIP;
    const int gcA = g * OUTCOLS - 4 + 2 * lane;   // even
    const int gcB = gcA + 1;
    const float mA = (gcA >= 0 && gcA < WW) ? 1.0f : 0.0f;
    const float mB = (gcB >= 0 && gcB < WW) ? 1.0f : 0.0f;
    const bool outLane = (lane >= 2) && (lane <= 29) && (gcA < WW);
    const int gca_c = min(max(gcA, 0), WW - 2);   // clamped, float2-safe
    const int pcol  = 2 * lane - 4;               // plane column for col A

    const float* xb = xg + (size_t)(b * CHAN + ch) * (HH * WW);
    const float* yb = yg + (size_t)(b * CHAN + ch) * (HH * WW);
    float* outp = outg + (size_t)b * (HH * WW);

    // interior flags (uniform per CTA)
    const bool cint = (g >= 1) && (g <= 8);               // all 64 cols in-image
    const bool rint = (strip >= 1) && (strip <= NSTRIPS - 2);  // rows r0-4..r0+71 in

    if (cint) {
        if (rint) zncc_tile<true,  true >(xb, yb, plane, outp, r0, g, tid, ch, lane, mA, mB, outLane, gca_c, pcol);
        else      zncc_tile<true,  false>(xb, yb, plane, outp, r0, g, tid, ch, lane, mA, mB, outLane, gca_c, pcol);
    } else {
        if (rint) zncc_tile<false, true >(xb, yb, plane, outp, r0, g, tid, ch, lane, mA, mB, outLane, gca_c, pcol);
        else      zncc_tile<false, false>(xb, yb, plane, outp, r0, g, tid, ch, lane, mA, mB, outLane, gca_c, pcol);
    }
}

extern "C" void kernel_launch(void* const* d_in, const int* in_sizes, int n_in,
                              void* d_out, int out_size)
{
    const float* x = (const float*)d_in[0];
    const float* y = (const float*)d_in[1];
    float* out = (float*)d_out;

    zncc_warp_kernel<<<NCTAS, 96>>>(x, y, out);
}

// round 14
// speedup vs baseline: 1.0447x; 1.0447x over previous
#include <cuda_runtime.h>

// ZNCC fused, warp-per-channel sliding-window (R12 mainloop) with a 16-row
// smem combine plane (combine twice per tile). smem/SM drops 200KB -> 100KB,
// so L1D (228KB - smem) grows to ~128KB and the per-step center-row reload
// actually hits L1 instead of spilling to L2.
// CTA = 96 threads = 3 warps; warp w handles channel w of one
// (batch, strip, col-group) tile: 64 raw cols (2/lane) x 32 output rows.
//
// math per pixel (zero-padded 5x5 means):
//   mx = box(x), my = box(y); xc = x-mx, yc = y-my (forced 0 outside image)
//   ncc = Sxy / (sqrt(Sxx*Syy) + 25e-8),  S* = 5x5 sums of products
//   out = mean_c(ncc)

#define HH 512
#define WW 512
#define CHAN 3
#define SSTRIP 32
#define PROWS 16                       // plane rows (half strip)
#define NSTRIPS (HH / SSTRIP)          // 16
#define OUTCOLS 56
#define NGROUPS 10                     // 10*56 = 560 >= 512
#define NBATCH 16
#define NCTAS (NGROUPS * NSTRIPS * NBATCH)   // 2560
#define PSTRIDE 58                     // plane row stride (even -> float2 ops)

// CINT: all 64 raw columns inside image (groups 1..8)
// RINT: all raw rows r0-4 .. r0+35 inside image (strips 1..14)
template<bool CINT, bool RINT>
__device__ __forceinline__ void zncc_tile(
    const float* __restrict__ xb, const float* __restrict__ yb,
    float (*planes)[PROWS][PSTRIDE],           // [CHAN][16][PSTRIDE]
    float* __restrict__ outp,                  // batch output base
    int r0, int g, int tid, int ch, int lane,
    float mA, float mB, bool outLane, int gca_c, int pcol)
{
    const unsigned FULL = 0xFFFFFFFFu;
    const float inv25 = 1.0f / 25.0f;
    const float inv3  = 1.0f / 3.0f;
    float (*plane)[PSTRIDE] = planes[ch];

    // combine the 3 channel planes for one 16-row half (fixed order -> det.)
    auto combine = [&](int half) {
        __syncthreads();   // all plane writes of this half done
        float* op = outp + (size_t)(r0 + PROWS * half) * WW + g * OUTCOLS;
        for (int idx = tid; idx < PROWS * (OUTCOLS / 2); idx += 96) {
            int row = idx / (OUTCOLS / 2);
            int c2  = idx - row * (OUTCOLS / 2);
            int col = 2 * c2;
            if (g * OUTCOLS + col < WW) {
                float2 p0 = *(const float2*)&planes[0][row][col];
                float2 p1 = *(const float2*)&planes[1][row][col];
                float2 p2 = *(const float2*)&planes[2][row][col];
                float2 v;
                v.x = (p0.x + p1.x + p2.x) * inv3;
                v.y = (p0.y + p1.y + p2.y) * inv3;
                *(float2*)&op[(size_t)row * WW + col] = v;
            }
        }
        __syncthreads();   // plane free for reuse
    };

    // ring buffers (indices static after unroll-by-5)
    float hxA[5], hxB[5], hyA[5], hyB[5];
    float qxyA[5], qxyB[5], qxxA[5], qxxB[5], qyyA[5], qyyB[5];
    #pragma unroll
    for (int i = 0; i < 5; i++) {
        hxA[i] = hxB[i] = hyA[i] = hyB[i] = 0.f;
        qxyA[i] = qxyB[i] = qxxA[i] = qxxB[i] = qyyA[i] = qyyB[i] = 0.f;
    }
    float sHxA = 0.f, sHxB = 0.f, sHyA = 0.f, sHyB = 0.f;

    // staged next-row values (software prefetch)
    float2 nvx = make_float2(0.f, 0.f), nvy = make_float2(0.f, 0.f);
    {
        const int t0 = r0 - 4;
        if (RINT || t0 >= 0) {
            nvx = *(const float2*)(xb + (size_t)t0 * WW + gca_c);
            nvy = *(const float2*)(yb + (size_t)t0 * WW + gca_c);
        }
    }

    for (int sb = 0; sb < SSTRIP + 8; sb += 5) {
        #pragma unroll
        for (int k = 0; k < 5; k++) {
            const int s = sb + k;                 // s % 5 == k
            const int t = r0 - 4 + s;             // raw row consumed now
            const int tn = t + 1;                 // prefetch target row

            // base address of row tn (used by prefetch and center reload)
            const float* xrow = xb + (size_t)tn * WW + gca_c;
            const float* yrow = yb + (size_t)tn * WW + gca_c;

            // ---- center row (t-2) reload: L1-resident (loaded 3 steps ago)
            float2 cvx, cvy;
            if (RINT) {
                cvx = *(const float2*)(xrow - 3 * WW);
                cvy = *(const float2*)(yrow - 3 * WW);
            } else {
                const int tcl = min(max(t - 2, 0), HH - 1);
                cvx = *(const float2*)(xb + (size_t)tcl * WW + gca_c);
                cvy = *(const float2*)(yb + (size_t)tcl * WW + gca_c);
            }

            // ---- consume staged row t, issue loads for row t+1 ----
            float vxA, vxB, vyA, vyB;
            if (CINT) {
                vxA = nvx.x; vxB = nvx.y;
                vyA = nvy.x; vyB = nvy.y;
            } else {
                vxA = nvx.x * mA; vxB = nvx.y * mB;
                vyA = nvy.x * mA; vyB = nvy.y * mB;
            }
            if (RINT || (unsigned)tn < (unsigned)HH) {
                nvx = *(const float2*)xrow;
                nvy = *(const float2*)yrow;
            } else {
                nvx = make_float2(0.f, 0.f);
                nvy = make_float2(0.f, 0.f);
            }
            if (!RINT) {
                if (t < 0) { vxA = vxB = vyA = vyB = 0.f; }
            }

            // ---- horizontal 5-sums of x,y via shuffles ----
            float vxAm = __shfl_up_sync(FULL, vxA, 1);
            float vxBm = __shfl_up_sync(FULL, vxB, 1);
            float vxAp = __shfl_down_sync(FULL, vxA, 1);
            float vxBp = __shfl_down_sync(FULL, vxB, 1);
            float cx   = vxBm + vxA + vxB + vxAp;
            float hxEn = cx + vxAm;               // col A (2l)
            float hxOn = cx + vxBp;               // col B (2l+1)

            float vyAm = __shfl_up_sync(FULL, vyA, 1);
            float vyBm = __shfl_up_sync(FULL, vyB, 1);
            float vyAp = __shfl_down_sync(FULL, vyA, 1);
            float vyBp = __shfl_down_sync(FULL, vyB, 1);
            float cy   = vyBm + vyA + vyB + vyAp;
            float hyEn = cy + vyAm;
            float hyOn = cy + vyBp;

            // ---- vertical sliding sums of h ----
            sHxA += hxEn - hxA[k]; hxA[k] = hxEn;
            sHxB += hxOn - hxB[k]; hxB[k] = hxOn;
            sHyA += hyEn - hyA[k]; hyA[k] = hyEn;
            sHyB += hyOn - hyB[k]; hyB[k] = hyOn;

            if (s >= 4) {
                // centered values at row tm = t-2 (center from L1 reload)
                float xcA, xcB, ycA, ycB;
                if (CINT && RINT) {
                    xcA = fmaf(sHxA, -inv25, cvx.x);
                    xcB = fmaf(sHxB, -inv25, cvx.y);
                    ycA = fmaf(sHyA, -inv25, cvy.x);
                    ycB = fmaf(sHyB, -inv25, cvy.y);
                } else {
                    const int tm = t - 2;
                    const float rm = (RINT || ((unsigned)tm < (unsigned)HH)) ? 1.0f : 0.0f;
                    const float fmA = CINT ? rm : mA * rm;
                    const float fmB = CINT ? rm : mB * rm;
                    xcA = fmaf(sHxA, -inv25, cvx.x) * fmA;
                    xcB = fmaf(sHxB, -inv25, cvx.y) * fmB;
                    ycA = fmaf(sHyA, -inv25, cvy.x) * fmA;
                    ycB = fmaf(sHyB, -inv25, cvy.y) * fmB;
                }

                // neighbors of xc,yc
                float xcAm = __shfl_up_sync(FULL, xcA, 1);
                float xcBm = __shfl_up_sync(FULL, xcB, 1);
                float xcAp = __shfl_down_sync(FULL, xcA, 1);
                float xcBp = __shfl_down_sync(FULL, xcB, 1);
                float ycAm = __shfl_up_sync(FULL, ycA, 1);
                float ycBm = __shfl_up_sync(FULL, ycB, 1);
                float ycAp = __shfl_down_sync(FULL, ycA, 1);
                float ycBp = __shfl_down_sync(FULL, ycB, 1);

                // horizontal 5-sums of products (shared middle-4 term)
                float c4xy = xcBm * ycBm + xcA * ycA + xcB * ycB + xcAp * ycAp;
                qxyA[k] = c4xy + xcAm * ycAm;
                qxyB[k] = c4xy + xcBp * ycBp;
                float c4xx = xcBm * xcBm + xcA * xcA + xcB * xcB + xcAp * xcAp;
                qxxA[k] = c4xx + xcAm * xcAm;
                qxxB[k] = c4xx + xcBp * xcBp;
                float c4yy = ycBm * ycBm + ycA * ycA + ycB * ycB + ycAp * ycAp;
                qyyA[k] = c4yy + ycAm * ycAm;
                qyyB[k] = c4yy + ycBp * ycBp;

                if (s >= 8) {
                    // direct 5-term vertical sums from the rings
                    float Sxy_A = ((qxyA[0] + qxyA[1]) + (qxyA[2] + qxyA[3])) + qxyA[4];
                    float Sxy_B = ((qxyB[0] + qxyB[1]) + (qxyB[2] + qxyB[3])) + qxyB[4];
                    float Sxx_A = ((qxxA[0] + qxxA[1]) + (qxxA[2] + qxxA[3])) + qxxA[4];
                    float Sxx_B = ((qxxB[0] + qxxB[1]) + (qxxB[2] + qxxB[3])) + qxxB[4];
                    float Syy_A = ((qyyA[0] + qyyA[1]) + (qyyA[2] + qyyA[3])) + qyyA[4];
                    float Syy_B = ((qyyB[0] + qyyB[1]) + (qyyB[2] + qyyB[3])) + qyyB[4];

                    const int prow = (s - 8) & (PROWS - 1);   // plane row
                    float dA = sqrtf(fmaxf(Sxx_A * Syy_A, 0.f)) + 2.5e-7f;
                    float dB = sqrtf(fmaxf(Sxx_B * Syy_B, 0.f)) + 2.5e-7f;
                    float nA = __fdividef(Sxy_A, dA);
                    float nB = __fdividef(Sxy_B, dB);
                    if (outLane) {
                        *(float2*)&plane[prow][pcol] = make_float2(nA, nB);
                    }
                    if (s == 8 + PROWS - 1) {     // rows 0..15 complete
                        combine(0);
                    }
                }
            }
        }
    }
    combine(1);                                   // rows 16..31
}

__global__ __launch_bounds__(96, 9)
void zncc_warp_kernel(const float* __restrict__ xg,
                      const float* __restrict__ yg,
                      float* __restrict__ outg)
{
    __shared__ float plane[CHAN][PROWS][PSTRIDE];   // 11.1 KB

    const int tid  = threadIdx.x;
    const int lane = tid & 31;
    const int ch   = tid >> 5;          // warp id == channel

    const int task  = blockIdx.x;
    const int b     = task / (NGROUPS * NSTRIPS);
    const int rem   = task - b * (NGROUPS * NSTRIPS);
    const int strip = rem / NGROUPS;
    const int g     = rem - strip * NGROUPS;

    const int r0  = strip * SSTRIP;
    const int gcA = g * OUTCOLS - 4 + 2 * lane;   // even
    const int gcB = gcA + 1;
    const float mA = (gcA >= 0 && gcA < WW) ? 1.0f : 0.0f;
    const float mB = (gcB >= 0 && gcB < WW) ? 1.0f : 0.0f;
    const bool outLane = (lane >= 2) && (lane <= 29) && (gcA < WW);
    const int gca_c = min(max(gcA, 0), WW - 2);   // clamped, float2-safe
    const int pcol  = 2 * lane - 4;               // plane column for col A

    const float* xb = xg + (size_t)(b * CHAN + ch) * (HH * WW);
    const float* yb = yg + (size_t)(b * CHAN + ch) * (HH * WW);
    float* outp = outg + (size_t)b * (HH * WW);

    // interior flags (uniform per CTA)
    const bool cint = (g >= 1) && (g <= 8);               // all 64 cols in-image
    const bool rint = (strip >= 1) && (strip <= NSTRIPS - 2);  // all rows in-image

    if (cint) {
        if (rint) zncc_tile<true,  true >(xb, yb, plane, outp, r0, g, tid, ch, lane, mA, mB, outLane, gca_c, pcol);
        else      zncc_tile<true,  false>(xb, yb, plane, outp, r0, g, tid, ch, lane, mA, mB, outLane, gca_c, pcol);
    } else {
        if (rint) zncc_tile<false, true >(xb, yb, plane, outp, r0, g, tid, ch, lane, mA, mB, outLane, gca_c, pcol);
        else      zncc_tile<false, false>(xb, yb, plane, outp, r0, g, tid, ch, lane, mA, mB, outLane, gca_c, pcol);
    }
}

extern "C" void kernel_launch(void* const* d_in, const int* in_sizes, int n_in,
                              void* d_out, int out_size)
{
    const float* x = (const float*)d_in[0];
    const float* y = (const float*)d_in[1];
    float* out = (float*)d_out;

    zncc_warp_kernel<<<NCTAS, 96>>>(x, y, out);
}